// round 6
// baseline (speedup 1.0000x reference)
#include <cuda_runtime.h>
#include <cstddef>
#include <cstdint>

#define N_NODES 100000
#define NNZ     3200000
#define SCAN_B  1024
#define SCAN_NB ((N_NODES + SCAN_B - 1) / SCAN_B)   // 98

// ---------------- static scratch (no allocation allowed) ----------------
//   sel 0: bA128 = arena                  (N*128 floats)
//   sel 1: bB128 = arena + N*128          (N*128 floats)
//   sel 2: b256  = arena + N*256          (N*256 floats)
__device__ float g_scratch[(size_t)N_NODES * 512];
__device__ int2  g_packed[NNZ];            // row-sorted (col, val-bits)
__device__ int   g_rowptr[N_NODES + 1];
__device__ int   g_wptr[N_NODES];
__device__ int   g_counts[N_NODES];
__device__ int   g_bsum[SCAN_NB];

__device__ __forceinline__ float* buf(int sel) {
    switch (sel) {
        case 0:  return g_scratch;
        case 1:  return g_scratch + (size_t)N_NODES * 128;
        default: return g_scratch + (size_t)N_NODES * 256;
    }
}

// ================= CSR build =================
__global__ void zero_counts_kernel() {
    int i = blockIdx.x * blockDim.x + threadIdx.x;
    if (i < N_NODES) g_counts[i] = 0;
}

__global__ void hist_kernel(const int* __restrict__ rows) {
    int e = blockIdx.x * blockDim.x + threadIdx.x;
    if (e < NNZ) atomicAdd(&g_counts[rows[e]], 1);
}

__global__ void __launch_bounds__(SCAN_B) scan1_kernel() {
    __shared__ int sh[SCAN_B];
    int t = threadIdx.x;
    int i = blockIdx.x * SCAN_B + t;
    int v = (i < N_NODES) ? g_counts[i] : 0;
    sh[t] = v;
    __syncthreads();
    #pragma unroll
    for (int off = 1; off < SCAN_B; off <<= 1) {
        int add = (t >= off) ? sh[t - off] : 0;
        __syncthreads();
        sh[t] += add;
        __syncthreads();
    }
    if (i < N_NODES) g_rowptr[i] = sh[t] - v;   // exclusive, block-local
    if (t == SCAN_B - 1) g_bsum[blockIdx.x] = sh[t];
}

__global__ void scan2_kernel() {   // exclusive scan of 98 block sums (1 warp)
    if (threadIdx.x == 0) {
        int acc = 0;
        for (int b = 0; b < SCAN_NB; b++) {
            int s = g_bsum[b];
            g_bsum[b] = acc;
            acc += s;
        }
    }
}

__global__ void scan3_kernel() {
    int i = blockIdx.x * blockDim.x + threadIdx.x;
    if (i < N_NODES) {
        int off = g_rowptr[i] + g_bsum[i / SCAN_B];
        g_rowptr[i] = off;
        g_wptr[i]   = off;
    }
    if (i == 0) g_rowptr[N_NODES] = NNZ;
}

__global__ void scatter_kernel(const int* __restrict__ rows,
                               const int* __restrict__ cols,
                               const float* __restrict__ vals) {
    int e = blockIdx.x * blockDim.x + threadIdx.x;
    if (e < NNZ) {
        int r = rows[e];
        int pos = atomicAdd(&g_wptr[r], 1);
        g_packed[pos] = make_int2(cols[e], __float_as_int(vals[e]));
    }
}

// ================= SpMM (d=128), CSR gather, warp per row =================
__global__ void __launch_bounds__(256) spmm_csr_kernel(
    const float* __restrict__ h_ext,
    float*       __restrict__ out_ext,
    int in_sel, int out_sel)
{
    const float* h   = (in_sel  < 0) ? h_ext   : buf(in_sel);
    float*       out = (out_sel < 0) ? out_ext : buf(out_sel);

    int row  = (int)((blockIdx.x * blockDim.x + threadIdx.x) >> 5);
    int lane = threadIdx.x & 31;
    if (row >= N_NODES) return;

    int e   = g_rowptr[row];
    int end = g_rowptr[row + 1];

    float4 acc = make_float4(0.f, 0.f, 0.f, 0.f);

    for (; e + 4 <= end; e += 4) {
        int2 p0 = __ldg(&g_packed[e + 0]);
        int2 p1 = __ldg(&g_packed[e + 1]);
        int2 p2 = __ldg(&g_packed[e + 2]);
        int2 p3 = __ldg(&g_packed[e + 3]);
        float4 g0 = __ldg((const float4*)(h + (size_t)p0.x * 128) + lane);
        float4 g1 = __ldg((const float4*)(h + (size_t)p1.x * 128) + lane);
        float4 g2 = __ldg((const float4*)(h + (size_t)p2.x * 128) + lane);
        float4 g3 = __ldg((const float4*)(h + (size_t)p3.x * 128) + lane);
        float v0 = __int_as_float(p0.y), v1 = __int_as_float(p1.y);
        float v2 = __int_as_float(p2.y), v3 = __int_as_float(p3.y);
        acc.x += v0 * g0.x; acc.y += v0 * g0.y; acc.z += v0 * g0.z; acc.w += v0 * g0.w;
        acc.x += v1 * g1.x; acc.y += v1 * g1.y; acc.z += v1 * g1.z; acc.w += v1 * g1.w;
        acc.x += v2 * g2.x; acc.y += v2 * g2.y; acc.z += v2 * g2.z; acc.w += v2 * g2.w;
        acc.x += v3 * g3.x; acc.y += v3 * g3.y; acc.z += v3 * g3.z; acc.w += v3 * g3.w;
    }
    for (; e < end; e++) {
        int2 p = __ldg(&g_packed[e]);
        float v = __int_as_float(p.y);
        float4 g = __ldg((const float4*)(h + (size_t)p.x * 128) + lane);
        acc.x += v * g.x; acc.y += v * g.y; acc.z += v * g.z; acc.w += v * g.w;
    }

    ((float4*)(out + (size_t)row * 128))[lane] = acc;
}

// ================= tf32 split GEMM: C = act(A[M,K] @ W[N,K]^T) =================
// 128x128x16 tile, 8 warps (2 warpM x 4 warpN), warp tile 64x32.
// 3-term tf32 split (hi*hi + hi*lo + lo*hi) -> fp32-level accuracy.
// Fragments pre-packed into smem in mma order -> conflict-free LDS.128/LDS.64.

#define MMA_TF32(c, a, b)                                                   \
    asm volatile("mma.sync.aligned.m16n8k8.row.col.f32.tf32.tf32.f32 "      \
        "{%0,%1,%2,%3},{%4,%5,%6,%7},{%8,%9},{%0,%1,%2,%3};"                \
        : "+f"((c)[0]), "+f"((c)[1]), "+f"((c)[2]), "+f"((c)[3])            \
        : "r"((a).x), "r"((a).y), "r"((a).z), "r"((a).w),                    \
          "r"((b).x), "r"((b).y));

__device__ __forceinline__ uint32_t f2tf32(float v) {
    uint32_t r;
    asm("cvt.rna.tf32.f32 %0, %1;" : "=r"(r) : "f"(v));
    return r;
}

template<int K, int N, bool RELU>
__global__ void __launch_bounds__(256) gemm_tf32(
    int a_sel,
    const float* __restrict__ W,
    float*       __restrict__ C_ext,
    int c_sel)
{
    const float* A = buf(a_sel);
    float*       C = (c_sel < 0) ? C_ext : buf(c_sel);

    constexpr int M = N_NODES, BM = 128, BN = 128, BK = 16;

    // fragment-packed smem: A [s2][wM2][mt4][lane32][reg4], B [s2][wN4][nt4][lane32][reg2]
    __shared__ uint32_t As_hi[2048], As_lo[2048];
    __shared__ uint32_t Bs_hi[2048], Bs_lo[2048];

    int tid  = threadIdx.x;
    int lane = tid & 31;
    int wid  = tid >> 5;
    int wM   = wid & 1;        // 0..1  (64 rows each)
    int wN   = wid >> 1;       // 0..3  (32 cols each)
    int gid  = lane >> 2;      // 0..7
    int tig  = lane & 3;       // 0..3

    int row0 = blockIdx.y * BM;
    int col0 = blockIdx.x * BN;

    // ---- loader mapping: thread owns 2 A rows and 2 B rows, one float4 of k ----
    int lrow = tid >> 2;       // 0..63
    int lcg  = tid & 3;        // col group: k = lcg*4 + j
    int ls   = lcg >> 1;       // k8 step (s)
    int lh   = lcg & 1;        // half within k8

    int l_mt  = lrow >> 4;     // mt for row lrow (wM differs between the 2 rows)
    int l_gid = lrow & 7;
    int l_rh  = (lrow >> 3) & 1;
    int a_reg   = lh * 2 + l_rh;
    int a_slot0 = ((ls * 2 + 0) * 4 + l_mt) * 32 + l_gid * 4;   // row lrow     (wM=0)
    int a_slot1 = ((ls * 2 + 1) * 4 + l_mt) * 32 + l_gid * 4;   // row lrow+64  (wM=1)

    int b_wn0 = lrow >> 5;
    int b_nt  = (lrow >> 3) & 3;
    int b_gid = lrow & 7;
    int b_reg   = lh;
    int b_slot0 = ((ls * 4 + b_wn0)     * 4 + b_nt) * 32 + b_gid * 4;  // n = lrow
    int b_slot1 = ((ls * 4 + b_wn0 + 2) * 4 + b_nt) * 32 + b_gid * 4;  // n = lrow+64

    float c[4][4][4] = {};     // [mt][nt][creg]

    float4 av0, av1, bv0, bv1;
    {
        int r0 = row0 + lrow;
        av0 = (r0      < M) ? *(const float4*)&A[(size_t)r0 * K + lcg * 4]        : make_float4(0,0,0,0);
        av1 = (r0 + 64 < M) ? *(const float4*)&A[(size_t)(r0 + 64) * K + lcg * 4] : make_float4(0,0,0,0);
        bv0 = *(const float4*)&W[(size_t)(col0 + lrow) * K + lcg * 4];
        bv1 = *(const float4*)&W[(size_t)(col0 + lrow + 64) * K + lcg * 4];
    }

    for (int k0 = 0; k0 < K; k0 += BK) {
        // ---- convert (hi/lo split) & store fragment-packed ----
        {
            const float* pa0 = &av0.x; const float* pa1 = &av1.x;
            const float* pb0 = &bv0.x; const float* pb1 = &bv1.x;
            #pragma unroll
            for (int j = 0; j < 4; j++) {
                float v; uint32_t h, l;
                v = pa0[j]; h = f2tf32(v); l = f2tf32(v - __uint_as_float(h));
                As_hi[(a_slot0 + j) * 4 + a_reg] = h;
                As_lo[(a_slot0 + j) * 4 + a_reg] = l;
                v = pa1[j]; h = f2tf32(v); l = f2tf32(v - __uint_as_float(h));
                As_hi[(a_slot1 + j) * 4 + a_reg] = h;
                As_lo[(a_slot1 + j) * 4 + a_reg] = l;
                v = pb0[j]; h = f2tf32(v); l = f2tf32(v - __uint_as_float(h));
                Bs_hi[(b_slot0 + j) * 2 + b_reg] = h;
                Bs_lo[(b_slot0 + j) * 2 + b_reg] = l;
                v = pb1[j]; h = f2tf32(v); l = f2tf32(v - __uint_as_float(h));
                Bs_hi[(b_slot1 + j) * 2 + b_reg] = h;
                Bs_lo[(b_slot1 + j) * 2 + b_reg] = l;
            }
        }
        __syncthreads();

        // prefetch next tile into registers (LDG overlapped with mma below)
        if (k0 + BK < K) {
            int r0 = row0 + lrow;
            av0 = (r0      < M) ? *(const float4*)&A[(size_t)r0 * K + k0 + BK + lcg * 4]        : make_float4(0,0,0,0);
            av1 = (r0 + 64 < M) ? *(const float4*)&A[(size_t)(r0 + 64) * K + k0 + BK + lcg * 4] : make_float4(0,0,0,0);
            bv0 = *(const float4*)&W[(size_t)(col0 + lrow) * K + k0 + BK + lcg * 4];
            bv1 = *(const float4*)&W[(size_t)(col0 + lrow + 64) * K + k0 + BK + lcg * 4];
        }

        // ---- mma phase ----
        #pragma unroll
        for (int s = 0; s < 2; s++) {
            uint4 ah[4], al[4]; uint2 bh[4], bl[4];
            #pragma unroll
            for (int mt = 0; mt < 4; mt++) {
                int sl = ((s * 2 + wM) * 4 + mt) * 32 + lane;
                ah[mt] = ((const uint4*)As_hi)[sl];
                al[mt] = ((const uint4*)As_lo)[sl];
            }
            #pragma unroll
            for (int nt = 0; nt < 4; nt++) {
                int sl = ((s * 4 + wN) * 4 + nt) * 32 + lane;
                bh[nt] = ((const uint2*)Bs_hi)[sl];
                bl[nt] = ((const uint2*)Bs_lo)[sl];
            }
            #pragma unroll
            for (int mt = 0; mt < 4; mt++)
                #pragma unroll
                for (int nt = 0; nt < 4; nt++) {
                    MMA_TF32(c[mt][nt], ah[mt], bh[nt]);
                    MMA_TF32(c[mt][nt], ah[mt], bl[nt]);
                    MMA_TF32(c[mt][nt], al[mt], bh[nt]);
                }
        }
        __syncthreads();
    }

    // ---- epilogue ----
    #pragma unroll
    for (int mt = 0; mt < 4; mt++) {
        int r_lo = row0 + wM * 64 + mt * 16 + gid;
        #pragma unroll
        for (int nt = 0; nt < 4; nt++) {
            int col = col0 + wN * 32 + nt * 8 + tig * 2;
            float2 o0, o1;
            o0.x = c[mt][nt][0]; o0.y = c[mt][nt][1];
            o1.x = c[mt][nt][2]; o1.y = c[mt][nt][3];
            if (RELU) {
                o0.x = fmaxf(o0.x, 0.f); o0.y = fmaxf(o0.y, 0.f);
                o1.x = fmaxf(o1.x, 0.f); o1.y = fmaxf(o1.y, 0.f);
            }
            if (r_lo < M)     *(float2*)&C[(size_t)r_lo * N + col]       = o0;
            if (r_lo + 8 < M) *(float2*)&C[(size_t)(r_lo + 8) * N + col] = o1;
        }
    }
}

// ---------------- launch ----------------
extern "C" void kernel_launch(void* const* d_in, const int* in_sizes, int n_in,
                              void* d_out, int out_size)
{
    const float* x  = (const float*)d_in[0];
    const int*   er = (const int*)  d_in[1];
    const int*   ec = (const int*)  d_in[2];
    const float* ev = (const float*)d_in[3];
    const float* W1 = (const float*)d_in[4];
    const float* W2 = (const float*)d_in[5];
    float* out = (float*)d_out;

    const int NB_N   = (N_NODES + 255) / 256;
    const int NB_E   = (NNZ + 255) / 256;
    const int NB_ROW = (N_NODES * 32 + 255) / 256;   // warp per row

    // ---- build CSR (row-sorted packed edges) ----
    zero_counts_kernel<<<NB_N, 256>>>();
    hist_kernel<<<NB_E, 256>>>(er);
    scan1_kernel<<<SCAN_NB, SCAN_B>>>();
    scan2_kernel<<<1, 32>>>();
    scan3_kernel<<<NB_N, 256>>>();
    scatter_kernel<<<NB_E, 256>>>(er, ec, ev);

    // ---- layer 1 propagation: s = A (A x)   (d=128, gather-only) ----
    spmm_csr_kernel<<<NB_ROW, 256>>>(x, nullptr, -1, 0);
    spmm_csr_kernel<<<NB_ROW, 256>>>(nullptr, nullptr, 0, 1);

    // h = relu(s @ W1^T) : [100000,128] x [256,128]^T -> b256
    {
        dim3 grid(256 / 128, (N_NODES + 127) / 128);
        gemm_tf32<128, 256, true><<<grid, 256>>>(1, W1, nullptr, 2);
    }

    // g = h @ W2^T : [100000,256] x [128,256]^T -> bA128
    // (exact reorder: (A^2 h) W2^T == A^2 (h W2^T), propagate at d=128)
    {
        dim3 grid(128 / 128, (N_NODES + 127) / 128);
        gemm_tf32<256, 128, false><<<grid, 256>>>(2, W2, nullptr, 0);
    }

    // ---- layer 2 propagation: out = A (A g)   (d=128) ----
    spmm_csr_kernel<<<NB_ROW, 256>>>(nullptr, nullptr, 0, 1);
    spmm_csr_kernel<<<NB_ROW, 256>>>(nullptr, out, 1, -1);
}

// round 7
// speedup vs baseline: 1.2663x; 1.2663x over previous
#include <cuda_runtime.h>
#include <cstddef>
#include <cstdint>

#define N_NODES 100000
#define NNZ     3200000
#define SCAN_B  1024
#define SCAN_NB ((N_NODES + SCAN_B - 1) / SCAN_B)   // 98

// ---------------- static scratch (no allocation allowed) ----------------
//   sel 0: bA128 = arena                  (N*128 floats)
//   sel 1: bB128 = arena + N*128          (N*128 floats)
//   sel 2: b256  = arena + N*256          (N*256 floats)
__device__ float g_scratch[(size_t)N_NODES * 512];
__device__ int2  g_packed[NNZ];            // row-sorted (col, val-bits)
__device__ int   g_rowptr[N_NODES + 1];
__device__ int   g_wptr[N_NODES];
__device__ int   g_counts[N_NODES];        // static-zero initially; scan1 re-zeroes
__device__ int   g_bsum[SCAN_NB];

__device__ __forceinline__ float* buf(int sel) {
    switch (sel) {
        case 0:  return g_scratch;
        case 1:  return g_scratch + (size_t)N_NODES * 128;
        default: return g_scratch + (size_t)N_NODES * 256;
    }
}

// ================= CSR build =================
__global__ void hist_kernel(const int* __restrict__ rows) {
    int e = blockIdx.x * blockDim.x + threadIdx.x;
    if (e < NNZ) atomicAdd(&g_counts[rows[e]], 1);
}

__global__ void __launch_bounds__(SCAN_B) scan1_kernel() {
    __shared__ int sh[SCAN_B];
    int t = threadIdx.x;
    int i = blockIdx.x * SCAN_B + t;
    int v = 0;
    if (i < N_NODES) {
        v = g_counts[i];
        g_counts[i] = 0;          // reset for next replay (deterministic)
    }
    sh[t] = v;
    __syncthreads();
    #pragma unroll
    for (int off = 1; off < SCAN_B; off <<= 1) {
        int add = (t >= off) ? sh[t - off] : 0;
        __syncthreads();
        sh[t] += add;
        __syncthreads();
    }
    if (i < N_NODES) g_rowptr[i] = sh[t] - v;   // exclusive, block-local
    if (t == SCAN_B - 1) g_bsum[blockIdx.x] = sh[t];
}

__global__ void __launch_bounds__(128) scan2_kernel() {  // exclusive scan of 98 sums
    __shared__ int sh[128];
    int t = threadIdx.x;
    int v = (t < SCAN_NB) ? g_bsum[t] : 0;
    sh[t] = v;
    __syncthreads();
    #pragma unroll
    for (int off = 1; off < 128; off <<= 1) {
        int add = (t >= off) ? sh[t - off] : 0;
        __syncthreads();
        sh[t] += add;
        __syncthreads();
    }
    if (t < SCAN_NB) g_bsum[t] = sh[t] - v;     // exclusive
}

__global__ void scan3_kernel() {
    int i = blockIdx.x * blockDim.x + threadIdx.x;
    if (i < N_NODES) {
        int off = g_rowptr[i] + g_bsum[i / SCAN_B];
        g_rowptr[i] = off;
        g_wptr[i]   = off;
    }
    if (i == 0) g_rowptr[N_NODES] = NNZ;
}

__global__ void scatter_kernel(const int* __restrict__ rows,
                               const int* __restrict__ cols,
                               const float* __restrict__ vals) {
    int e = blockIdx.x * blockDim.x + threadIdx.x;
    if (e < NNZ) {
        int r = rows[e];
        int pos = atomicAdd(&g_wptr[r], 1);
        g_packed[pos] = make_int2(cols[e], __float_as_int(vals[e]));
    }
}

// ================= SpMM (d=128), CSR gather, warp per row =================
__device__ __forceinline__ int2 ldcs_int2(const int2* p) {
    int2 r;
    asm volatile("ld.global.cs.v2.s32 {%0,%1}, [%2];"
                 : "=r"(r.x), "=r"(r.y) : "l"(p));
    return r;
}

__global__ void __launch_bounds__(256) spmm_csr_kernel(
    const float* __restrict__ h_ext,
    float*       __restrict__ out_ext,
    int in_sel, int out_sel)
{
    const float* h   = (in_sel  < 0) ? h_ext   : buf(in_sel);
    float*       out = (out_sel < 0) ? out_ext : buf(out_sel);

    int row  = (int)((blockIdx.x * blockDim.x + threadIdx.x) >> 5);
    int lane = threadIdx.x & 31;
    if (row >= N_NODES) return;

    int e   = g_rowptr[row];
    int end = g_rowptr[row + 1];

    float4 acc = make_float4(0.f, 0.f, 0.f, 0.f);

    for (; e + 4 <= end; e += 4) {
        int2 p0 = ldcs_int2(&g_packed[e + 0]);
        int2 p1 = ldcs_int2(&g_packed[e + 1]);
        int2 p2 = ldcs_int2(&g_packed[e + 2]);
        int2 p3 = ldcs_int2(&g_packed[e + 3]);
        float4 g0 = __ldg((const float4*)(h + (size_t)p0.x * 128) + lane);
        float4 g1 = __ldg((const float4*)(h + (size_t)p1.x * 128) + lane);
        float4 g2 = __ldg((const float4*)(h + (size_t)p2.x * 128) + lane);
        float4 g3 = __ldg((const float4*)(h + (size_t)p3.x * 128) + lane);
        float v0 = __int_as_float(p0.y), v1 = __int_as_float(p1.y);
        float v2 = __int_as_float(p2.y), v3 = __int_as_float(p3.y);
        acc.x += v0 * g0.x; acc.y += v0 * g0.y; acc.z += v0 * g0.z; acc.w += v0 * g0.w;
        acc.x += v1 * g1.x; acc.y += v1 * g1.y; acc.z += v1 * g1.z; acc.w += v1 * g1.w;
        acc.x += v2 * g2.x; acc.y += v2 * g2.y; acc.z += v2 * g2.z; acc.w += v2 * g2.w;
        acc.x += v3 * g3.x; acc.y += v3 * g3.y; acc.z += v3 * g3.z; acc.w += v3 * g3.w;
    }
    for (; e < end; e++) {
        int2 p = ldcs_int2(&g_packed[e]);
        float v = __int_as_float(p.y);
        float4 g = __ldg((const float4*)(h + (size_t)p.x * 128) + lane);
        acc.x += v * g.x; acc.y += v * g.y; acc.z += v * g.z; acc.w += v * g.w;
    }

    ((float4*)(out + (size_t)row * 128))[lane] = acc;
}

// ================= tf32 GEMM (single-term): C = act(A[M,K] @ W[N,K]^T) =================
// 128x128x16 tile, 8 warps (2 warpM x 4 warpN), warp tile 64x32.
// Fragments pre-packed into smem in mma order -> conflict-free LDS.128/LDS.64.

#define MMA_TF32(c, a, b)                                                   \
    asm volatile("mma.sync.aligned.m16n8k8.row.col.f32.tf32.tf32.f32 "      \
        "{%0,%1,%2,%3},{%4,%5,%6,%7},{%8,%9},{%0,%1,%2,%3};"                \
        : "+f"((c)[0]), "+f"((c)[1]), "+f"((c)[2]), "+f"((c)[3])            \
        : "r"((a).x), "r"((a).y), "r"((a).z), "r"((a).w),                    \
          "r"((b).x), "r"((b).y));

__device__ __forceinline__ uint32_t f2tf32(float v) {
    uint32_t r;
    asm("cvt.rna.tf32.f32 %0, %1;" : "=r"(r) : "f"(v));
    return r;
}

template<int K, int N, bool RELU>
__global__ void __launch_bounds__(256) gemm_tf32(
    int a_sel,
    const float* __restrict__ W,
    float*       __restrict__ C_ext,
    int c_sel)
{
    const float* A = buf(a_sel);
    float*       C = (c_sel < 0) ? C_ext : buf(c_sel);

    constexpr int M = N_NODES, BM = 128, BN = 128, BK = 16;

    // fragment-packed smem: A [s2][wM2][mt4][lane32][reg4], B [s2][wN4][nt4][lane32][reg2]
    __shared__ uint32_t As_hi[2048];
    __shared__ uint32_t Bs_hi[2048];

    int tid  = threadIdx.x;
    int lane = tid & 31;
    int wid  = tid >> 5;
    int wM   = wid & 1;        // 0..1  (64 rows each)
    int wN   = wid >> 1;       // 0..3  (32 cols each)
    int gid  = lane >> 2;      // 0..7
    int tig  = lane & 3;       // 0..3

    int row0 = blockIdx.y * BM;
    int col0 = blockIdx.x * BN;

    // ---- loader mapping: thread owns 2 A rows and 2 B rows, one float4 of k ----
    int lrow = tid >> 2;       // 0..63
    int lcg  = tid & 3;        // col group: k = lcg*4 + j
    int ls   = lcg >> 1;       // k8 step (s)
    int lh   = lcg & 1;        // half within k8

    int l_mt  = lrow >> 4;
    int l_gid = lrow & 7;
    int l_rh  = (lrow >> 3) & 1;
    int a_reg   = lh * 2 + l_rh;
    int a_slot0 = ((ls * 2 + 0) * 4 + l_mt) * 32 + l_gid * 4;   // row lrow     (wM=0)
    int a_slot1 = ((ls * 2 + 1) * 4 + l_mt) * 32 + l_gid * 4;   // row lrow+64  (wM=1)

    int b_wn0 = lrow >> 5;
    int b_nt  = (lrow >> 3) & 3;
    int b_gid = lrow & 7;
    int b_reg   = lh;
    int b_slot0 = ((ls * 4 + b_wn0)     * 4 + b_nt) * 32 + b_gid * 4;  // n = lrow
    int b_slot1 = ((ls * 4 + b_wn0 + 2) * 4 + b_nt) * 32 + b_gid * 4;  // n = lrow+64

    float c[4][4][4] = {};     // [mt][nt][creg]

    float4 av0, av1, bv0, bv1;
    {
        int r0 = row0 + lrow;
        av0 = (r0      < M) ? *(const float4*)&A[(size_t)r0 * K + lcg * 4]        : make_float4(0,0,0,0);
        av1 = (r0 + 64 < M) ? *(const float4*)&A[(size_t)(r0 + 64) * K + lcg * 4] : make_float4(0,0,0,0);
        bv0 = *(const float4*)&W[(size_t)(col0 + lrow) * K + lcg * 4];
        bv1 = *(const float4*)&W[(size_t)(col0 + lrow + 64) * K + lcg * 4];
    }

    for (int k0 = 0; k0 < K; k0 += BK) {
        // ---- convert & store fragment-packed ----
        {
            const float* pa0 = &av0.x; const float* pa1 = &av1.x;
            const float* pb0 = &bv0.x; const float* pb1 = &bv1.x;
            #pragma unroll
            for (int j = 0; j < 4; j++) {
                As_hi[(a_slot0 + j) * 4 + a_reg] = f2tf32(pa0[j]);
                As_hi[(a_slot1 + j) * 4 + a_reg] = f2tf32(pa1[j]);
                Bs_hi[(b_slot0 + j) * 2 + b_reg] = f2tf32(pb0[j]);
                Bs_hi[(b_slot1 + j) * 2 + b_reg] = f2tf32(pb1[j]);
            }
        }
        __syncthreads();

        // prefetch next tile into registers (LDG overlapped with mma below)
        if (k0 + BK < K) {
            int r0 = row0 + lrow;
            av0 = (r0      < M) ? *(const float4*)&A[(size_t)r0 * K + k0 + BK + lcg * 4]        : make_float4(0,0,0,0);
            av1 = (r0 + 64 < M) ? *(const float4*)&A[(size_t)(r0 + 64) * K + k0 + BK + lcg * 4] : make_float4(0,0,0,0);
            bv0 = *(const float4*)&W[(size_t)(col0 + lrow) * K + k0 + BK + lcg * 4];
            bv1 = *(const float4*)&W[(size_t)(col0 + lrow + 64) * K + k0 + BK + lcg * 4];
        }

        // ---- mma phase ----
        #pragma unroll
        for (int s = 0; s < 2; s++) {
            uint4 ah[4]; uint2 bh[4];
            #pragma unroll
            for (int mt = 0; mt < 4; mt++) {
                int sl = ((s * 2 + wM) * 4 + mt) * 32 + lane;
                ah[mt] = ((const uint4*)As_hi)[sl];
            }
            #pragma unroll
            for (int nt = 0; nt < 4; nt++) {
                int sl = ((s * 4 + wN) * 4 + nt) * 32 + lane;
                bh[nt] = ((const uint2*)Bs_hi)[sl];
            }
            #pragma unroll
            for (int mt = 0; mt < 4; mt++)
                #pragma unroll
                for (int nt = 0; nt < 4; nt++)
                    MMA_TF32(c[mt][nt], ah[mt], bh[nt]);
        }
        __syncthreads();
    }

    // ---- epilogue ----
    #pragma unroll
    for (int mt = 0; mt < 4; mt++) {
        int r_lo = row0 + wM * 64 + mt * 16 + gid;
        #pragma unroll
        for (int nt = 0; nt < 4; nt++) {
            int col = col0 + wN * 32 + nt * 8 + tig * 2;
            float2 o0, o1;
            o0.x = c[mt][nt][0]; o0.y = c[mt][nt][1];
            o1.x = c[mt][nt][2]; o1.y = c[mt][nt][3];
            if (RELU) {
                o0.x = fmaxf(o0.x, 0.f); o0.y = fmaxf(o0.y, 0.f);
                o1.x = fmaxf(o1.x, 0.f); o1.y = fmaxf(o1.y, 0.f);
            }
            if (r_lo < M)     *(float2*)&C[(size_t)r_lo * N + col]       = o0;
            if (r_lo + 8 < M) *(float2*)&C[(size_t)(r_lo + 8) * N + col] = o1;
        }
    }
}

// ---------------- launch ----------------
extern "C" void kernel_launch(void* const* d_in, const int* in_sizes, int n_in,
                              void* d_out, int out_size)
{
    const float* x  = (const float*)d_in[0];
    const int*   er = (const int*)  d_in[1];
    const int*   ec = (const int*)  d_in[2];
    const float* ev = (const float*)d_in[3];
    const float* W1 = (const float*)d_in[4];
    const float* W2 = (const float*)d_in[5];
    float* out = (float*)d_out;

    const int NB_N   = (N_NODES + 255) / 256;
    const int NB_E   = (NNZ + 255) / 256;
    const int NB_ROW = (N_NODES * 32 + 255) / 256;   // warp per row

    // ---- build CSR (row-sorted packed edges) ----
    hist_kernel<<<NB_E, 256>>>(er);
    scan1_kernel<<<SCAN_NB, SCAN_B>>>();
    scan2_kernel<<<1, 128>>>();
    scan3_kernel<<<NB_N, 256>>>();
    scatter_kernel<<<NB_E, 256>>>(er, ec, ev);

    // ---- layer 1 propagation: s = A (A x)   (d=128, gather-only) ----
    spmm_csr_kernel<<<NB_ROW, 256>>>(x, nullptr, -1, 0);
    spmm_csr_kernel<<<NB_ROW, 256>>>(nullptr, nullptr, 0, 1);

    // h = relu(s @ W1^T) : [100000,128] x [256,128]^T -> b256
    {
        dim3 grid(256 / 128, (N_NODES + 127) / 128);
        gemm_tf32<128, 256, true><<<grid, 256>>>(1, W1, nullptr, 2);
    }

    // g = h @ W2^T : [100000,256] x [128,256]^T -> bA128
    // (exact reorder: (A^2 h) W2^T == A^2 (h W2^T), propagate at d=128)
    {
        dim3 grid(128 / 128, (N_NODES + 127) / 128);
        gemm_tf32<256, 128, false><<<grid, 256>>>(2, W2, nullptr, 0);
    }

    // ---- layer 2 propagation: out = A (A g)   (d=128) ----
    spmm_csr_kernel<<<NB_ROW, 256>>>(nullptr, nullptr, 0, 1);
    spmm_csr_kernel<<<NB_ROW, 256>>>(nullptr, out, 1, -1);
}

// round 8
// speedup vs baseline: 1.6770x; 1.3243x over previous
#include <cuda_runtime.h>
#include <cuda_fp16.h>
#include <cstddef>
#include <cstdint>

#define N_NODES 100000
#define NNZ     3200000
#define SCAN_B  1024
#define SCAN_NB ((N_NODES + SCAN_B - 1) / SCAN_B)   // 98

// ---------------- static scratch (no allocation allowed) ----------------
// fp16 feature arena:
//   sel 0: x16   [0,      N*128)
//   sel 1: hb1   [N*128,  N*256)   (spmm ping)
//   sel 2: hb2   [N*256,  N*384)   (spmm pong / gemm1 A)
//   sel 3: hbg   [N*384,  N*512)   (gemm2 out)
//   sel 4: h256  [N*512,  N*768)   (gemm1 out / gemm2 A)
__device__ __half g_h16[(size_t)N_NODES * 768];
__device__ int2   g_packed[NNZ];            // row-sorted (col, val-bits)
__device__ int    g_rowptr[N_NODES + 1];
__device__ int    g_wptr[N_NODES];
__device__ int    g_counts[N_NODES];        // static-zero; scan1 re-zeroes
__device__ int    g_bsum[SCAN_NB];

__device__ __forceinline__ __half* hbuf(int sel) {
    return g_h16 + (size_t)N_NODES * 128 * sel;   // sel 4 = offset N*512 ✓
}

__device__ __forceinline__ uint32_t pack2(float a, float b) {
    __half2 h = __floats2half2_rn(a, b);
    return *(uint32_t*)&h;
}

// ================= CSR build =================
__global__ void hist_kernel(const int* __restrict__ rows) {
    int e = blockIdx.x * blockDim.x + threadIdx.x;
    if (e < NNZ) atomicAdd(&g_counts[rows[e]], 1);
}

__global__ void __launch_bounds__(SCAN_B) scan1_kernel() {
    __shared__ int sh[SCAN_B];
    int t = threadIdx.x;
    int i = blockIdx.x * SCAN_B + t;
    int v = 0;
    if (i < N_NODES) {
        v = g_counts[i];
        g_counts[i] = 0;          // reset for next replay (deterministic)
    }
    sh[t] = v;
    __syncthreads();
    #pragma unroll
    for (int off = 1; off < SCAN_B; off <<= 1) {
        int add = (t >= off) ? sh[t - off] : 0;
        __syncthreads();
        sh[t] += add;
        __syncthreads();
    }
    if (i < N_NODES) g_rowptr[i] = sh[t] - v;
    if (t == SCAN_B - 1) g_bsum[blockIdx.x] = sh[t];
}

__global__ void __launch_bounds__(128) scan2_kernel() {
    __shared__ int sh[128];
    int t = threadIdx.x;
    int v = (t < SCAN_NB) ? g_bsum[t] : 0;
    sh[t] = v;
    __syncthreads();
    #pragma unroll
    for (int off = 1; off < 128; off <<= 1) {
        int add = (t >= off) ? sh[t - off] : 0;
        __syncthreads();
        sh[t] += add;
        __syncthreads();
    }
    if (t < SCAN_NB) g_bsum[t] = sh[t] - v;
}

__global__ void scan3_kernel() {
    int i = blockIdx.x * blockDim.x + threadIdx.x;
    if (i < N_NODES) {
        int off = g_rowptr[i] + g_bsum[i / SCAN_B];
        g_rowptr[i] = off;
        g_wptr[i]   = off;
    }
    if (i == 0) g_rowptr[N_NODES] = NNZ;
}

__global__ void scatter_kernel(const int* __restrict__ rows,
                               const int* __restrict__ cols,
                               const float* __restrict__ vals) {
    int e = blockIdx.x * blockDim.x + threadIdx.x;
    if (e < NNZ) {
        int r = rows[e];
        int pos = atomicAdd(&g_wptr[r], 1);
        g_packed[pos] = make_int2(cols[e], __float_as_int(vals[e]));
    }
}

// ================= x (fp32) -> fp16 =================
__global__ void cvt_x_kernel(const float* __restrict__ x) {
    size_t i = (size_t)blockIdx.x * blockDim.x + threadIdx.x;
    if (i < (size_t)N_NODES * 128 / 4) {
        float4 v = __ldg((const float4*)x + i);
        uint2 w;
        w.x = pack2(v.x, v.y);
        w.y = pack2(v.z, v.w);
        ((uint2*)hbuf(0))[i] = w;
    }
}

// ================= SpMM (d=128, fp16 gather, fp32 accum) =================
__device__ __forceinline__ int2 ldcs_int2(const int2* p) {
    int2 r;
    asm volatile("ld.global.cs.v2.s32 {%0,%1}, [%2];"
                 : "=r"(r.x), "=r"(r.y) : "l"(p));
    return r;
}

__device__ __forceinline__ float4 h4_to_f4(uint2 r) {
    __half2 a = *(__half2*)&r.x;
    __half2 b = *(__half2*)&r.y;
    float2 f0 = __half22float2(a);
    float2 f1 = __half22float2(b);
    return make_float4(f0.x, f0.y, f1.x, f1.y);
}

__global__ void __launch_bounds__(256) spmm16_kernel(
    int in_sel, int out_sel, float* __restrict__ out32)
{
    const __half* h = hbuf(in_sel);

    int row  = (int)((blockIdx.x * blockDim.x + threadIdx.x) >> 5);
    int lane = threadIdx.x & 31;
    if (row >= N_NODES) return;

    int e   = g_rowptr[row];
    int end = g_rowptr[row + 1];

    float4 acc = make_float4(0.f, 0.f, 0.f, 0.f);

    for (; e + 4 <= end; e += 4) {
        int2 p0 = ldcs_int2(&g_packed[e + 0]);
        int2 p1 = ldcs_int2(&g_packed[e + 1]);
        int2 p2 = ldcs_int2(&g_packed[e + 2]);
        int2 p3 = ldcs_int2(&g_packed[e + 3]);
        uint2 r0 = __ldg((const uint2*)(h + (size_t)p0.x * 128) + lane);
        uint2 r1 = __ldg((const uint2*)(h + (size_t)p1.x * 128) + lane);
        uint2 r2 = __ldg((const uint2*)(h + (size_t)p2.x * 128) + lane);
        uint2 r3 = __ldg((const uint2*)(h + (size_t)p3.x * 128) + lane);
        float4 g0 = h4_to_f4(r0), g1 = h4_to_f4(r1);
        float4 g2 = h4_to_f4(r2), g3 = h4_to_f4(r3);
        float v0 = __int_as_float(p0.y), v1 = __int_as_float(p1.y);
        float v2 = __int_as_float(p2.y), v3 = __int_as_float(p3.y);
        acc.x += v0 * g0.x; acc.y += v0 * g0.y; acc.z += v0 * g0.z; acc.w += v0 * g0.w;
        acc.x += v1 * g1.x; acc.y += v1 * g1.y; acc.z += v1 * g1.z; acc.w += v1 * g1.w;
        acc.x += v2 * g2.x; acc.y += v2 * g2.y; acc.z += v2 * g2.z; acc.w += v2 * g2.w;
        acc.x += v3 * g3.x; acc.y += v3 * g3.y; acc.z += v3 * g3.z; acc.w += v3 * g3.w;
    }
    for (; e < end; e++) {
        int2 p = ldcs_int2(&g_packed[e]);
        float v = __int_as_float(p.y);
        float4 g = h4_to_f4(__ldg((const uint2*)(h + (size_t)p.x * 128) + lane));
        acc.x += v * g.x; acc.y += v * g.y; acc.z += v * g.z; acc.w += v * g.w;
    }

    if (out_sel >= 0) {
        uint2 w;
        w.x = pack2(acc.x, acc.y);
        w.y = pack2(acc.z, acc.w);
        ((uint2*)(hbuf(out_sel) + (size_t)row * 128))[lane] = w;
    } else {
        ((float4*)(out32 + (size_t)row * 128))[lane] = acc;
    }
}

// ================= fp16 GEMM: C16 = act(A16[M,K] @ W32[N,K]^T) =================
// 128x128x32 tile, 8 warps (2 wM x 4 wN), warp tile 64x32.
// ldmatrix from padded smem (stride 40 halves -> conflict-free), mma.m16n8k16.

#define LDSM_X4(r0, r1, r2, r3, addr)                                        \
    asm volatile("ldmatrix.sync.aligned.m8n8.x4.shared.b16 {%0,%1,%2,%3}, [%4];" \
        : "=r"(r0), "=r"(r1), "=r"(r2), "=r"(r3) : "r"(addr));

#define MMA_F16(c, a, b)                                                     \
    asm volatile("mma.sync.aligned.m16n8k16.row.col.f32.f16.f16.f32 "        \
        "{%0,%1,%2,%3},{%4,%5,%6,%7},{%8,%9},{%0,%1,%2,%3};"                 \
        : "+f"((c)[0]), "+f"((c)[1]), "+f"((c)[2]), "+f"((c)[3])             \
        : "r"((a)[0]), "r"((a)[1]), "r"((a)[2]), "r"((a)[3]),                \
          "r"((b)[0]), "r"((b)[1]));

template<int K, int N, bool RELU>
__global__ void __launch_bounds__(256) gemm_f16(
    int a_sel, const float* __restrict__ W, int c_sel)
{
    const __half* A = hbuf(a_sel);
    __half*       C = hbuf(c_sel);

    constexpr int M = N_NODES, BM = 128, BK = 32, LDA = 40;

    __shared__ __align__(16) uint16_t As[BM * LDA];
    __shared__ __align__(16) uint16_t Bs[BM * LDA];

    int tid  = threadIdx.x;
    int lane = tid & 31;
    int wid  = tid >> 5;
    int wM   = wid & 1;
    int wN   = wid >> 1;

    int row0 = blockIdx.y * BM;
    int col0 = blockIdx.x * BM;     // BN == BM == 128

    // loader: thread -> row lr (0..127), k-half lc (0..1), 16 halves each
    int lr = tid >> 1;
    int lc = tid & 1;

    // ldmatrix lane addressing (x4): group -> (row-half, k-half)
    int grp     = lane >> 3;
    int rl      = lane & 7;
    int lm_roff = (grp & 1) * 8 + rl;
    int lm_koff = (grp >> 1) * 8;

    float c[4][4][4] = {};

    uint4 pa0, pa1, pb0, pb1;

    // ---- initial prefetch (k0 = 0) ----
    {
        int r = row0 + lr;
        if (r < M) {
            pa0 = *(const uint4*)(A + (size_t)r * K + lc * 16 + 0);
            pa1 = *(const uint4*)(A + (size_t)r * K + lc * 16 + 8);
        } else {
            pa0 = make_uint4(0, 0, 0, 0);
            pa1 = make_uint4(0, 0, 0, 0);
        }
        const float* wp = W + (size_t)(col0 + lr) * K + lc * 16;
        float4 w0 = *(const float4*)(wp + 0);
        float4 w1 = *(const float4*)(wp + 4);
        float4 w2 = *(const float4*)(wp + 8);
        float4 w3 = *(const float4*)(wp + 12);
        pb0 = make_uint4(pack2(w0.x, w0.y), pack2(w0.z, w0.w),
                         pack2(w1.x, w1.y), pack2(w1.z, w1.w));
        pb1 = make_uint4(pack2(w2.x, w2.y), pack2(w2.z, w2.w),
                         pack2(w3.x, w3.y), pack2(w3.z, w3.w));
    }

    for (int k0 = 0; k0 < K; k0 += BK) {
        // ---- commit prefetched tile to smem ----
        *(uint4*)&As[lr * LDA + lc * 16 + 0] = pa0;
        *(uint4*)&As[lr * LDA + lc * 16 + 8] = pa1;
        *(uint4*)&Bs[lr * LDA + lc * 16 + 0] = pb0;
        *(uint4*)&Bs[lr * LDA + lc * 16 + 8] = pb1;
        __syncthreads();

        // ---- prefetch next tile ----
        if (k0 + BK < K) {
            int r = row0 + lr;
            if (r < M) {
                pa0 = *(const uint4*)(A + (size_t)r * K + k0 + BK + lc * 16 + 0);
                pa1 = *(const uint4*)(A + (size_t)r * K + k0 + BK + lc * 16 + 8);
            } else {
                pa0 = make_uint4(0, 0, 0, 0);
                pa1 = make_uint4(0, 0, 0, 0);
            }
            const float* wp = W + (size_t)(col0 + lr) * K + k0 + BK + lc * 16;
            float4 w0 = *(const float4*)(wp + 0);
            float4 w1 = *(const float4*)(wp + 4);
            float4 w2 = *(const float4*)(wp + 8);
            float4 w3 = *(const float4*)(wp + 12);
            pb0 = make_uint4(pack2(w0.x, w0.y), pack2(w0.z, w0.w),
                             pack2(w1.x, w1.y), pack2(w1.z, w1.w));
            pb1 = make_uint4(pack2(w2.x, w2.y), pack2(w2.z, w2.w),
                             pack2(w3.x, w3.y), pack2(w3.z, w3.w));
        }

        // ---- mma phase: 2 k16 steps ----
        #pragma unroll
        for (int s = 0; s < 2; s++) {
            uint32_t a[4][4], b[4][2];
            #pragma unroll
            for (int mt = 0; mt < 4; mt++) {
                uint32_t sa = (uint32_t)__cvta_generic_to_shared(
                    &As[(wM * 64 + mt * 16 + lm_roff) * LDA + s * 16 + lm_koff]);
                LDSM_X4(a[mt][0], a[mt][1], a[mt][2], a[mt][3], sa);
            }
            #pragma unroll
            for (int ntp = 0; ntp < 2; ntp++) {
                uint32_t sb = (uint32_t)__cvta_generic_to_shared(
                    &Bs[(wN * 32 + ntp * 16 + lm_roff) * LDA + s * 16 + lm_koff]);
                uint32_t r0, r1, r2, r3;
                LDSM_X4(r0, r1, r2, r3, sb);
                b[2 * ntp][0]     = r0;
                b[2 * ntp + 1][0] = r1;
                b[2 * ntp][1]     = r2;
                b[2 * ntp + 1][1] = r3;
            }
            #pragma unroll
            for (int mt = 0; mt < 4; mt++)
                #pragma unroll
                for (int nt = 0; nt < 4; nt++)
                    MMA_F16(c[mt][nt], a[mt], b[nt]);
        }
        __syncthreads();
    }

    // ---- epilogue: fp32 acc -> fp16 store ----
    int gid = lane >> 2;
    int tig = lane & 3;
    #pragma unroll
    for (int mt = 0; mt < 4; mt++) {
        int r = row0 + wM * 64 + mt * 16 + gid;
        #pragma unroll
        for (int nt = 0; nt < 4; nt++) {
            int col = col0 + wN * 32 + nt * 8 + tig * 2;
            float v0 = c[mt][nt][0], v1 = c[mt][nt][1];
            float v2 = c[mt][nt][2], v3 = c[mt][nt][3];
            if (RELU) {
                v0 = fmaxf(v0, 0.f); v1 = fmaxf(v1, 0.f);
                v2 = fmaxf(v2, 0.f); v3 = fmaxf(v3, 0.f);
            }
            if (r < M)
                *(uint32_t*)&C[(size_t)r * N + col] = pack2(v0, v1);
            if (r + 8 < M)
                *(uint32_t*)&C[(size_t)(r + 8) * N + col] = pack2(v2, v3);
        }
    }
}

// ---------------- launch ----------------
extern "C" void kernel_launch(void* const* d_in, const int* in_sizes, int n_in,
                              void* d_out, int out_size)
{
    const float* x  = (const float*)d_in[0];
    const int*   er = (const int*)  d_in[1];
    const int*   ec = (const int*)  d_in[2];
    const float* ev = (const float*)d_in[3];
    const float* W1 = (const float*)d_in[4];
    const float* W2 = (const float*)d_in[5];
    float* out = (float*)d_out;

    const int NB_N   = (N_NODES + 255) / 256;
    const int NB_E   = (NNZ + 255) / 256;
    const int NB_ROW = (N_NODES * 32 + 255) / 256;   // warp per row
    const int NB_CVT = (N_NODES * 128 / 4 + 255) / 256;

    // ---- build CSR + convert x (independent; CSR first is fine) ----
    hist_kernel<<<NB_E, 256>>>(er);
    cvt_x_kernel<<<NB_CVT, 256>>>(x);
    scan1_kernel<<<SCAN_NB, SCAN_B>>>();
    scan2_kernel<<<1, 128>>>();
    scan3_kernel<<<NB_N, 256>>>();
    scatter_kernel<<<NB_E, 256>>>(er, ec, ev);

    // ---- layer 1 propagation: s = A (A x16)  : sel0 -> sel1 -> sel2 ----
    spmm16_kernel<<<NB_ROW, 256>>>(0, 1, nullptr);
    spmm16_kernel<<<NB_ROW, 256>>>(1, 2, nullptr);

    // h = relu(s @ W1^T) : [100000,128] x [256,128]^T -> sel4 [100000,256]
    {
        dim3 grid(2, (N_NODES + 127) / 128);
        gemm_f16<128, 256, true><<<grid, 256>>>(2, W1, 4);
    }

    // g = h @ W2^T : [100000,256] x [128,256]^T -> sel3 [100000,128]
    // (exact reorder: (A^2 h) W2^T == A^2 (h W2^T), propagate at d=128)
    {
        dim3 grid(1, (N_NODES + 127) / 128);
        gemm_f16<256, 128, false><<<grid, 256>>>(4, W2, 3);
    }

    // ---- layer 2 propagation: out = A (A g) : sel3 -> sel1 -> d_out(fp32) ----
    spmm16_kernel<<<NB_ROW, 256>>>(3, 1, nullptr);
    spmm16_kernel<<<NB_ROW, 256>>>(1, -1, out);
}

// round 9
// speedup vs baseline: 1.7269x; 1.0297x over previous
#include <cuda_runtime.h>
#include <cuda_fp16.h>
#include <cstddef>
#include <cstdint>

#define N_NODES 100000
#define NNZ     3200000
#define SCAN_B  1024
#define SCAN_NB ((N_NODES + SCAN_B - 1) / SCAN_B)   // 98

// ---------------- static scratch (no allocation allowed) ----------------
// fp16 feature arena:
//   sel 0: x16   [0,      N*128)
//   sel 1: hb1   [N*128,  N*256)   (spmm ping)
//   sel 2: hb2   [N*256,  N*384)   (spmm pong / fused-gemm in)
//   sel 3: hbg   [N*384,  N*512)   (fused-gemm out)
__device__ __half g_h16[(size_t)N_NODES * 512];
__device__ int2   g_packed[NNZ];            // row-sorted (col, val-bits)
__device__ int    g_rowptr[N_NODES + 1];
__device__ int    g_wptr[N_NODES];
__device__ int    g_counts[N_NODES];        // static-zero; scan1 re-zeroes
__device__ int    g_bsum[SCAN_NB];

__device__ __forceinline__ __half* hbuf(int sel) {
    return g_h16 + (size_t)N_NODES * 128 * sel;
}

__device__ __forceinline__ uint32_t pack2(float a, float b) {
    __half2 h = __floats2half2_rn(a, b);
    return *(uint32_t*)&h;
}

// ================= CSR build =================
__device__ __forceinline__ int ldcs_i(const int* p) {
    int r; asm volatile("ld.global.cs.s32 %0, [%1];" : "=r"(r) : "l"(p)); return r;
}
__device__ __forceinline__ float ldcs_f(const float* p) {
    float r; asm volatile("ld.global.cs.f32 %0, [%1];" : "=f"(r) : "l"(p)); return r;
}

__global__ void hist_kernel(const int* __restrict__ rows) {
    int e = blockIdx.x * blockDim.x + threadIdx.x;
    if (e < NNZ) atomicAdd(&g_counts[ldcs_i(rows + e)], 1);
}

__global__ void __launch_bounds__(SCAN_B) scan1_kernel() {
    __shared__ int sh[SCAN_B];
    int t = threadIdx.x;
    int i = blockIdx.x * SCAN_B + t;
    int v = 0;
    if (i < N_NODES) {
        v = g_counts[i];
        g_counts[i] = 0;          // reset for next replay (deterministic)
    }
    sh[t] = v;
    __syncthreads();
    #pragma unroll
    for (int off = 1; off < SCAN_B; off <<= 1) {
        int add = (t >= off) ? sh[t - off] : 0;
        __syncthreads();
        sh[t] += add;
        __syncthreads();
    }
    if (i < N_NODES) g_rowptr[i] = sh[t] - v;
    if (t == SCAN_B - 1) g_bsum[blockIdx.x] = sh[t];
}

__global__ void __launch_bounds__(128) scan2_kernel() {
    __shared__ int sh[128];
    int t = threadIdx.x;
    int v = (t < SCAN_NB) ? g_bsum[t] : 0;
    sh[t] = v;
    __syncthreads();
    #pragma unroll
    for (int off = 1; off < 128; off <<= 1) {
        int add = (t >= off) ? sh[t - off] : 0;
        __syncthreads();
        sh[t] += add;
        __syncthreads();
    }
    if (t < SCAN_NB) g_bsum[t] = sh[t] - v;
}

__global__ void scan3_kernel() {
    int i = blockIdx.x * blockDim.x + threadIdx.x;
    if (i < N_NODES) {
        int off = g_rowptr[i] + g_bsum[i / SCAN_B];
        g_rowptr[i] = off;
        g_wptr[i]   = off;
    }
    if (i == 0) g_rowptr[N_NODES] = NNZ;
}

__global__ void scatter_kernel(const int* __restrict__ rows,
                               const int* __restrict__ cols,
                               const float* __restrict__ vals) {
    int e = blockIdx.x * blockDim.x + threadIdx.x;
    if (e < NNZ) {
        int r = ldcs_i(rows + e);
        int c = ldcs_i(cols + e);
        float v = ldcs_f(vals + e);
        int pos = atomicAdd(&g_wptr[r], 1);
        g_packed[pos] = make_int2(c, __float_as_int(v));
    }
}

// ================= x (fp32) -> fp16 =================
__global__ void cvt_x_kernel(const float* __restrict__ x) {
    size_t i = (size_t)blockIdx.x * blockDim.x + threadIdx.x;
    if (i < (size_t)N_NODES * 128 / 4) {
        float4 v = __ldg((const float4*)x + i);
        uint2 w;
        w.x = pack2(v.x, v.y);
        w.y = pack2(v.z, v.w);
        ((uint2*)hbuf(0))[i] = w;
    }
}

// ================= SpMM (d=128, fp16 gather, fp32 accum) =================
__device__ __forceinline__ int2 ldcs_int2(const int2* p) {
    int2 r;
    asm volatile("ld.global.cs.v2.s32 {%0,%1}, [%2];"
                 : "=r"(r.x), "=r"(r.y) : "l"(p));
    return r;
}

__device__ __forceinline__ float4 h4_to_f4(uint2 r) {
    __half2 a = *(__half2*)&r.x;
    __half2 b = *(__half2*)&r.y;
    float2 f0 = __half22float2(a);
    float2 f1 = __half22float2(b);
    return make_float4(f0.x, f0.y, f1.x, f1.y);
}

__global__ void __launch_bounds__(256) spmm16_kernel(
    int in_sel, int out_sel, float* __restrict__ out32)
{
    const __half* h = hbuf(in_sel);

    int row  = (int)((blockIdx.x * blockDim.x + threadIdx.x) >> 5);
    int lane = threadIdx.x & 31;
    if (row >= N_NODES) return;

    int e   = g_rowptr[row];
    int end = g_rowptr[row + 1];

    float4 acc = make_float4(0.f, 0.f, 0.f, 0.f);

    for (; e + 8 <= end; e += 8) {
        int2 p[8]; uint2 r[8];
        #pragma unroll
        for (int j = 0; j < 8; j++) p[j] = ldcs_int2(&g_packed[e + j]);
        #pragma unroll
        for (int j = 0; j < 8; j++)
            r[j] = __ldg((const uint2*)(h + (size_t)p[j].x * 128) + lane);
        #pragma unroll
        for (int j = 0; j < 8; j++) {
            float v = __int_as_float(p[j].y);
            float4 g = h4_to_f4(r[j]);
            acc.x += v * g.x; acc.y += v * g.y;
            acc.z += v * g.z; acc.w += v * g.w;
        }
    }
    for (; e < end; e++) {
        int2 p = ldcs_int2(&g_packed[e]);
        float v = __int_as_float(p.y);
        float4 g = h4_to_f4(__ldg((const uint2*)(h + (size_t)p.x * 128) + lane));
        acc.x += v * g.x; acc.y += v * g.y; acc.z += v * g.z; acc.w += v * g.w;
    }

    if (out_sel >= 0) {
        uint2 w;
        w.x = pack2(acc.x, acc.y);
        w.y = pack2(acc.z, acc.w);
        ((uint2*)(hbuf(out_sel) + (size_t)row * 128))[lane] = w;
    } else {
        ((float4*)(out32 + (size_t)row * 128))[lane] = acc;
    }
}

// ================= fused GEMM: g = (relu(s @ W1^T)) @ W2^T =================
// Per block: 128 rows. Stage A: h[128x256] = relu(s[128x128] @ W1[256x128]^T),
// fp32 accum -> fp16 in smem. Stage B: g[128x128] = h @ W2[128x256]^T.
// Dynamic smem: Hs 128x264 halves (67584B) + As 128x40 (10240B) + Bs 256x40 (20480B).

#define LDSM_X4(r0, r1, r2, r3, addr)                                        \
    asm volatile("ldmatrix.sync.aligned.m8n8.x4.shared.b16 {%0,%1,%2,%3}, [%4];" \
        : "=r"(r0), "=r"(r1), "=r"(r2), "=r"(r3) : "r"(addr));

#define MMA_F16(c, a, b)                                                     \
    asm volatile("mma.sync.aligned.m16n8k16.row.col.f32.f16.f16.f32 "        \
        "{%0,%1,%2,%3},{%4,%5,%6,%7},{%8,%9},{%0,%1,%2,%3};"                 \
        : "+f"((c)[0]), "+f"((c)[1]), "+f"((c)[2]), "+f"((c)[3])             \
        : "r"((a)[0]), "r"((a)[1]), "r"((a)[2]), "r"((a)[3]),                \
          "r"((b)[0]), "r"((b)[1]));

#define LDH   264            // Hs row stride in halves (per-phase conflict-free)
#define SMEM_FUSED (128 * LDH * 2 + 128 * 40 * 2 + 256 * 40 * 2)

__global__ void __launch_bounds__(256) gemm_fused_kernel(
    int a_sel, const float* __restrict__ W1, const float* __restrict__ W2,
    int c_sel)
{
    const __half* A = hbuf(a_sel);
    __half*       C = hbuf(c_sel);

    constexpr int M = N_NODES, LDA = 40;

    extern __shared__ __align__(16) uint8_t dsm[];
    uint16_t* Hs = (uint16_t*)dsm;                         // 128 x LDH
    uint16_t* As = (uint16_t*)(dsm + 128 * LDH * 2);       // 128 x 40
    uint16_t* Bs = (uint16_t*)(dsm + 128 * LDH * 2 + 128 * 40 * 2); // 256 x 40

    int tid  = threadIdx.x;
    int lane = tid & 31;
    int wid  = tid >> 5;
    int wM   = wid & 1;        // rows wM*64..
    int wN   = wid >> 1;       // 0..3

    int row0 = blockIdx.x * 128;

    int gid = lane >> 2;
    int tig = lane & 3;

    // ldmatrix lane addressing (x4)
    int grp     = lane >> 3;
    int rl      = lane & 7;
    int lm_roff = (grp & 1) * 8 + rl;
    int lm_koff = (grp >> 1) * 8;

    // A loader: row lr (0..127), k-half lc (0..1), 16 halves
    int lr = tid >> 1;
    int lc = tid & 1;

    // ============ STAGE A: h = relu(s @ W1^T), K=128, N=256 ============
    {
        float c[4][8][4] = {};

        uint4 pa0, pa1;        // A prefetch (16 halves)
        uint4 pb[4];           // W1 prefetch: row tid, 32 k -> 32 halves

        // initial prefetch (k0 = 0)
        {
            int r = row0 + lr;
            if (r < M) {
                pa0 = *(const uint4*)(A + (size_t)r * 128 + lc * 16 + 0);
                pa1 = *(const uint4*)(A + (size_t)r * 128 + lc * 16 + 8);
            } else { pa0 = make_uint4(0,0,0,0); pa1 = make_uint4(0,0,0,0); }
            const float* wp = W1 + (size_t)tid * 128;
            #pragma unroll
            for (int q = 0; q < 4; q++) {
                float4 w0 = *(const float4*)(wp + q * 8 + 0);
                float4 w1 = *(const float4*)(wp + q * 8 + 4);
                pb[q] = make_uint4(pack2(w0.x, w0.y), pack2(w0.z, w0.w),
                                   pack2(w1.x, w1.y), pack2(w1.z, w1.w));
            }
        }

        for (int k0 = 0; k0 < 128; k0 += 32) {
            *(uint4*)&As[lr * LDA + lc * 16 + 0] = pa0;
            *(uint4*)&As[lr * LDA + lc * 16 + 8] = pa1;
            #pragma unroll
            for (int q = 0; q < 4; q++)
                *(uint4*)&Bs[tid * LDA + q * 8] = pb[q];
            __syncthreads();

            if (k0 + 32 < 128) {
                int r = row0 + lr;
                if (r < M) {
                    pa0 = *(const uint4*)(A + (size_t)r * 128 + k0 + 32 + lc * 16 + 0);
                    pa1 = *(const uint4*)(A + (size_t)r * 128 + k0 + 32 + lc * 16 + 8);
                } else { pa0 = make_uint4(0,0,0,0); pa1 = make_uint4(0,0,0,0); }
                const float* wp = W1 + (size_t)tid * 128 + k0 + 32;
                #pragma unroll
                for (int q = 0; q < 4; q++) {
                    float4 w0 = *(const float4*)(wp + q * 8 + 0);
                    float4 w1 = *(const float4*)(wp + q * 8 + 4);
                    pb[q] = make_uint4(pack2(w0.x, w0.y), pack2(w0.z, w0.w),
                                       pack2(w1.x, w1.y), pack2(w1.z, w1.w));
                }
            }

            #pragma unroll
            for (int s = 0; s < 2; s++) {
                uint32_t a[4][4], b[8][2];
                #pragma unroll
                for (int mt = 0; mt < 4; mt++) {
                    uint32_t sa = (uint32_t)__cvta_generic_to_shared(
                        &As[(wM * 64 + mt * 16 + lm_roff) * LDA + s * 16 + lm_koff]);
                    LDSM_X4(a[mt][0], a[mt][1], a[mt][2], a[mt][3], sa);
                }
                #pragma unroll
                for (int ntp = 0; ntp < 4; ntp++) {
                    uint32_t sb = (uint32_t)__cvta_generic_to_shared(
                        &Bs[(wN * 64 + ntp * 16 + lm_roff) * LDA + s * 16 + lm_koff]);
                    uint32_t r0, r1, r2, r3;
                    LDSM_X4(r0, r1, r2, r3, sb);
                    b[2 * ntp][0]     = r0;
                    b[2 * ntp + 1][0] = r1;
                    b[2 * ntp][1]     = r2;
                    b[2 * ntp + 1][1] = r3;
                }
                #pragma unroll
                for (int mt = 0; mt < 4; mt++)
                    #pragma unroll
                    for (int nt = 0; nt < 8; nt++)
                        MMA_F16(c[mt][nt], a[mt], b[nt]);
            }
            __syncthreads();
        }

        // relu + write h (fp16) to Hs
        #pragma unroll
        for (int mt = 0; mt < 4; mt++) {
            int r = wM * 64 + mt * 16 + gid;
            #pragma unroll
            for (int nt = 0; nt < 8; nt++) {
                int col = wN * 64 + nt * 8 + tig * 2;
                float v0 = fmaxf(c[mt][nt][0], 0.f), v1 = fmaxf(c[mt][nt][1], 0.f);
                float v2 = fmaxf(c[mt][nt][2], 0.f), v3 = fmaxf(c[mt][nt][3], 0.f);
                *(uint32_t*)&Hs[r * LDH + col]       = pack2(v0, v1);
                *(uint32_t*)&Hs[(r + 8) * LDH + col] = pack2(v2, v3);
            }
        }
    }
    __syncthreads();

    // ============ STAGE B: g = h @ W2^T, K=256, N=128 ============
    {
        float c[4][4][4] = {};

        uint4 pb0, pb1;    // W2 prefetch: row lr, 16 halves
        {
            const float* wp = W2 + (size_t)lr * 256 + lc * 16;
            float4 w0 = *(const float4*)(wp + 0);
            float4 w1 = *(const float4*)(wp + 4);
            float4 w2 = *(const float4*)(wp + 8);
            float4 w3 = *(const float4*)(wp + 12);
            pb0 = make_uint4(pack2(w0.x, w0.y), pack2(w0.z, w0.w),
                             pack2(w1.x, w1.y), pack2(w1.z, w1.w));
            pb1 = make_uint4(pack2(w2.x, w2.y), pack2(w2.z, w2.w),
                             pack2(w3.x, w3.y), pack2(w3.z, w3.w));
        }

        for (int k0 = 0; k0 < 256; k0 += 32) {
            *(uint4*)&Bs[lr * LDA + lc * 16 + 0] = pb0;
            *(uint4*)&Bs[lr * LDA + lc * 16 + 8] = pb1;
            __syncthreads();

            if (k0 + 32 < 256) {
                const float* wp = W2 + (size_t)lr * 256 + k0 + 32 + lc * 16;
                float4 w0 = *(const float4*)(wp + 0);
                float4 w1 = *(const float4*)(wp + 4);
                float4 w2 = *(const float4*)(wp + 8);
                float4 w3 = *(const float4*)(wp + 12);
                pb0 = make_uint4(pack2(w0.x, w0.y), pack2(w0.z, w0.w),
                                 pack2(w1.x, w1.y), pack2(w1.z, w1.w));
                pb1 = make_uint4(pack2(w2.x, w2.y), pack2(w2.z, w2.w),
                                 pack2(w3.x, w3.y), pack2(w3.z, w3.w));
            }

            #pragma unroll
            for (int s = 0; s < 2; s++) {
                uint32_t a[4][4], b[4][2];
                #pragma unroll
                for (int mt = 0; mt < 4; mt++) {
                    uint32_t sa = (uint32_t)__cvta_generic_to_shared(
                        &Hs[(wM * 64 + mt * 16 + lm_roff) * LDH + k0 + s * 16 + lm_koff]);
                    LDSM_X4(a[mt][0], a[mt][1], a[mt][2], a[mt][3], sa);
                }
                #pragma unroll
                for (int ntp = 0; ntp < 2; ntp++) {
                    uint32_t sb = (uint32_t)__cvta_generic_to_shared(
                        &Bs[(wN * 32 + ntp * 16 + lm_roff) * LDA + s * 16 + lm_koff]);
                    uint32_t r0, r1, r2, r3;
                    LDSM_X4(r0, r1, r2, r3, sb);
                    b[2 * ntp][0]     = r0;
                    b[2 * ntp + 1][0] = r1;
                    b[2 * ntp][1]     = r2;
                    b[2 * ntp + 1][1] = r3;
                }
                #pragma unroll
                for (int mt = 0; mt < 4; mt++)
                    #pragma unroll
                    for (int nt = 0; nt < 4; nt++)
                        MMA_F16(c[mt][nt], a[mt], b[nt]);
            }
            __syncthreads();
        }

        // epilogue: g (fp16) to C
        #pragma unroll
        for (int mt = 0; mt < 4; mt++) {
            int r = row0 + wM * 64 + mt * 16 + gid;
            #pragma unroll
            for (int nt = 0; nt < 4; nt++) {
                int col = wN * 32 + nt * 8 + tig * 2;
                if (r < M)
                    *(uint32_t*)&C[(size_t)r * 128 + col] = pack2(c[mt][nt][0], c[mt][nt][1]);
                if (r + 8 < M)
                    *(uint32_t*)&C[(size_t)(r + 8) * 128 + col] = pack2(c[mt][nt][2], c[mt][nt][3]);
            }
        }
    }
}

// ---------------- launch ----------------
extern "C" void kernel_launch(void* const* d_in, const int* in_sizes, int n_in,
                              void* d_out, int out_size)
{
    const float* x  = (const float*)d_in[0];
    const int*   er = (const int*)  d_in[1];
    const int*   ec = (const int*)  d_in[2];
    const float* ev = (const float*)d_in[3];
    const float* W1 = (const float*)d_in[4];
    const float* W2 = (const float*)d_in[5];
    float* out = (float*)d_out;

    const int NB_N   = (N_NODES + 255) / 256;
    const int NB_E   = (NNZ + 255) / 256;
    const int NB_ROW = (N_NODES * 32 + 255) / 256;   // warp per row
    const int NB_CVT = (N_NODES * 128 / 4 + 255) / 256;

    cudaFuncSetAttribute(gemm_fused_kernel,
                         cudaFuncAttributeMaxDynamicSharedMemorySize, SMEM_FUSED);

    // ---- build CSR + convert x ----
    hist_kernel<<<NB_E, 256>>>(er);
    cvt_x_kernel<<<NB_CVT, 256>>>(x);
    scan1_kernel<<<SCAN_NB, SCAN_B>>>();
    scan2_kernel<<<1, 128>>>();
    scan3_kernel<<<NB_N, 256>>>();
    scatter_kernel<<<NB_E, 256>>>(er, ec, ev);

    // ---- layer 1 propagation: s = A (A x16)  : sel0 -> sel1 -> sel2 ----
    spmm16_kernel<<<NB_ROW, 256>>>(0, 1, nullptr);
    spmm16_kernel<<<NB_ROW, 256>>>(1, 2, nullptr);

    // ---- fused: g = relu(s @ W1^T) @ W2^T : sel2 -> sel3 ----
    // (exact reorder: (A^2 h) W2^T == A^2 (h W2^T), propagate at d=128)
    gemm_fused_kernel<<<(N_NODES + 127) / 128, 256, SMEM_FUSED>>>(2, W1, W2, 3);

    // ---- layer 2 propagation: out = A (A g) : sel3 -> sel1 -> d_out(fp32) ----
    spmm16_kernel<<<NB_ROW, 256>>>(3, 1, nullptr);
    spmm16_kernel<<<NB_ROW, 256>>>(1, -1, out);
}

// round 12
// speedup vs baseline: 1.8267x; 1.0578x over previous
#include <cuda_runtime.h>
#include <cuda_fp16.h>
#include <cstddef>
#include <cstdint>

#define N_NODES 100000
#define NNZ     3200000
#define SCAN_B  1024
#define SCAN_NB ((N_NODES + SCAN_B - 1) / SCAN_B)   // 98

// ---------------- static scratch (no allocation allowed) ----------------
// fp16 feature arena:
//   sel 0: x16   [0,      N*128)
//   sel 1: hb1   [N*128,  N*256)   (spmm ping)
//   sel 2: hb2   [N*256,  N*384)   (spmm pong / fused-gemm in)
//   sel 3: hbg   [N*384,  N*512)   (fused-gemm out)
__device__ __half g_h16[(size_t)N_NODES * 512];
__device__ int2   g_packed[NNZ];            // row-sorted (col, val-bits)
__device__ int    g_rowptr[N_NODES + 1];
__device__ int    g_wptr[N_NODES];
__device__ int    g_counts[N_NODES];        // static-zero; scan1 re-zeroes
__device__ int    g_bsum[SCAN_NB];

__device__ __forceinline__ __half* hbuf(int sel) {
    return g_h16 + (size_t)N_NODES * 128 * sel;
}

__device__ __forceinline__ uint32_t pack2(float a, float b) {
    __half2 h = __floats2half2_rn(a, b);
    return *(uint32_t*)&h;
}

// ================= CSR build =================
__device__ __forceinline__ int ldcs_i(const int* p) {
    int r; asm volatile("ld.global.cs.s32 %0, [%1];" : "=r"(r) : "l"(p)); return r;
}
__device__ __forceinline__ float ldcs_f(const float* p) {
    float r; asm volatile("ld.global.cs.f32 %0, [%1];" : "=f"(r) : "l"(p)); return r;
}

// hist + x->fp16 convert fused: both are exactly NNZ (=N*128/4) threads of work.
__global__ void hist_cvt_kernel(const int* __restrict__ rows,
                                const float* __restrict__ x) {
    size_t e = (size_t)blockIdx.x * blockDim.x + threadIdx.x;
    if (e < NNZ) {
        atomicAdd(&g_counts[ldcs_i(rows + e)], 1);
        float4 v = __ldg((const float4*)x + e);
        uint2 w;
        w.x = pack2(v.x, v.y);
        w.y = pack2(v.z, v.w);
        ((uint2*)hbuf(0))[e] = w;
    }
}

__global__ void __launch_bounds__(SCAN_B) scan1_kernel() {
    __shared__ int sh[SCAN_B];
    int t = threadIdx.x;
    int i = blockIdx.x * SCAN_B + t;
    int v = 0;
    if (i < N_NODES) {
        v = g_counts[i];
        g_counts[i] = 0;          // reset for next replay (deterministic)
    }
    sh[t] = v;
    __syncthreads();
    #pragma unroll
    for (int off = 1; off < SCAN_B; off <<= 1) {
        int add = (t >= off) ? sh[t - off] : 0;
        __syncthreads();
        sh[t] += add;
        __syncthreads();
    }
    if (i < N_NODES) g_rowptr[i] = sh[t] - v;
    if (t == SCAN_B - 1) g_bsum[blockIdx.x] = sh[t];
}

// scan3 with inlined global prefix: each 256-thread block covers one bsum bucket
// (4 blocks per SCAN_B bucket, 256*4 == 1024), so bi is constant per block and
// the block reduces bsum[0..bi) itself (<=98 values < 256 threads).
__global__ void __launch_bounds__(256) scan3_kernel() {
    __shared__ int sh[256];
    __shared__ int prefix;
    int t  = threadIdx.x;
    int i  = blockIdx.x * 256 + t;
    int bi = (blockIdx.x * 256) / SCAN_B;    // constant per block

    int v = (t < bi) ? g_bsum[t] : 0;        // bi <= 98 < 256
    sh[t] = v;
    __syncthreads();
    #pragma unroll
    for (int off = 128; off > 0; off >>= 1) {
        if (t < off) sh[t] += sh[t + off];
        __syncthreads();
    }
    if (t == 0) prefix = sh[0];
    __syncthreads();

    if (i < N_NODES) {
        int off = g_rowptr[i] + prefix;
        g_rowptr[i] = off;
        g_wptr[i]   = off;
    }
    if (i == 0) g_rowptr[N_NODES] = NNZ;
}

__global__ void scatter_kernel(const int* __restrict__ rows,
                               const int* __restrict__ cols,
                               const float* __restrict__ vals) {
    int e = blockIdx.x * blockDim.x + threadIdx.x;
    if (e < NNZ) {
        int r = ldcs_i(rows + e);
        int c = ldcs_i(cols + e);
        float v = ldcs_f(vals + e);
        int pos = atomicAdd(&g_wptr[r], 1);
        g_packed[pos] = make_int2(c, __float_as_int(v));
    }
}

// ================= SpMM (d=128, fp16 gather, fp32 accum) =================
__device__ __forceinline__ int2 ldcs_int2(const int2* p) {
    int2 r;
    asm volatile("ld.global.cs.v2.s32 {%0,%1}, [%2];"
                 : "=r"(r.x), "=r"(r.y) : "l"(p));
    return r;
}

__device__ __forceinline__ float4 h4_to_f4(uint2 r) {
    __half2 a = *(__half2*)&r.x;
    __half2 b = *(__half2*)&r.y;
    float2 f0 = __half22float2(a);
    float2 f1 = __half22float2(b);
    return make_float4(f0.x, f0.y, f1.x, f1.y);
}

__global__ void __launch_bounds__(256) spmm16_kernel(
    int in_sel, int out_sel, float* __restrict__ out32)
{
    const __half* h = hbuf(in_sel);

    int row  = (int)((blockIdx.x * blockDim.x + threadIdx.x) >> 5);
    int lane = threadIdx.x & 31;
    if (row >= N_NODES) return;

    int e   = g_rowptr[row];
    int end = g_rowptr[row + 1];

    float4 acc = make_float4(0.f, 0.f, 0.f, 0.f);

    for (; e + 8 <= end; e += 8) {
        int2 p[8]; uint2 r[8];
        #pragma unroll
        for (int j = 0; j < 8; j++) p[j] = ldcs_int2(&g_packed[e + j]);
        #pragma unroll
        for (int j = 0; j < 8; j++)
            r[j] = __ldg((const uint2*)(h + (size_t)p[j].x * 128) + lane);
        #pragma unroll
        for (int j = 0; j < 8; j++) {
            float v = __int_as_float(p[j].y);
            float4 g = h4_to_f4(r[j]);
            acc.x += v * g.x; acc.y += v * g.y;
            acc.z += v * g.z; acc.w += v * g.w;
        }
    }
    for (; e < end; e++) {
        int2 p = ldcs_int2(&g_packed[e]);
        float v = __int_as_float(p.y);
        float4 g = h4_to_f4(__ldg((const uint2*)(h + (size_t)p.x * 128) + lane));
        acc.x += v * g.x; acc.y += v * g.y; acc.z += v * g.z; acc.w += v * g.w;
    }

    if (out_sel >= 0) {
        uint2 w;
        w.x = pack2(acc.x, acc.y);
        w.y = pack2(acc.z, acc.w);
        ((uint2*)(hbuf(out_sel) + (size_t)row * 128))[lane] = w;
    } else {
        ((float4*)(out32 + (size_t)row * 128))[lane] = acc;
    }
}

// ================= fused GEMM: g = (relu(s @ W1^T)) @ W2^T =================
// Double-buffered smem pipeline; one __syncthreads per k-iter.
// Layout: Hs 128x264 (67584B) | As0 (10240) | As1 (10240) | Bs0 (20480) | Bs1 (20480)

#define LDSM_X4(r0, r1, r2, r3, addr)                                        \
    asm volatile("ldmatrix.sync.aligned.m8n8.x4.shared.b16 {%0,%1,%2,%3}, [%4];" \
        : "=r"(r0), "=r"(r1), "=r"(r2), "=r"(r3) : "r"(addr));

#define MMA_F16(c, a, b)                                                     \
    asm volatile("mma.sync.aligned.m16n8k16.row.col.f32.f16.f16.f32 "        \
        "{%0,%1,%2,%3},{%4,%5,%6,%7},{%8,%9},{%0,%1,%2,%3};"                 \
        : "+f"((c)[0]), "+f"((c)[1]), "+f"((c)[2]), "+f"((c)[3])             \
        : "r"((a)[0]), "r"((a)[1]), "r"((a)[2]), "r"((a)[3]),                \
          "r"((b)[0]), "r"((b)[1]));

#define LDH   264
#define HS_BYTES  (128 * LDH * 2)
#define AS_BYTES  (128 * 40 * 2)
#define BS_BYTES  (256 * 40 * 2)
#define SMEM_FUSED (HS_BYTES + 2 * AS_BYTES + 2 * BS_BYTES)   // 129024

__global__ void __launch_bounds__(256) gemm_fused_kernel(
    int a_sel, const float* __restrict__ W1, const float* __restrict__ W2,
    int c_sel)
{
    const __half* A = hbuf(a_sel);
    __half*       C = hbuf(c_sel);

    constexpr int M = N_NODES, LDA = 40;

    extern __shared__ __align__(16) uint8_t dsm[];
    uint16_t* Hs = (uint16_t*)dsm;
    uint16_t* Asb[2] = { (uint16_t*)(dsm + HS_BYTES),
                         (uint16_t*)(dsm + HS_BYTES + AS_BYTES) };
    uint16_t* Bsb[2] = { (uint16_t*)(dsm + HS_BYTES + 2 * AS_BYTES),
                         (uint16_t*)(dsm + HS_BYTES + 2 * AS_BYTES + BS_BYTES) };

    int tid  = threadIdx.x;
    int lane = tid & 31;
    int wid  = tid >> 5;
    int wM   = wid & 1;
    int wN   = wid >> 1;

    int row0 = blockIdx.x * 128;

    int gid = lane >> 2;
    int tig = lane & 3;

    int grp     = lane >> 3;
    int rl      = lane & 7;
    int lm_roff = (grp & 1) * 8 + rl;
    int lm_koff = (grp >> 1) * 8;

    int lr = tid >> 1;
    int lc = tid & 1;

    // ============ STAGE A: h = relu(s @ W1^T), K=128, N=256 ============
    {
        float c[4][8][4] = {};

        uint4 pa0, pa1;        // A prefetch (16 halves)
        uint4 pb[4];           // W1 prefetch: row tid, 32 halves

        // prefetch k0 = 0
        {
            int r = row0 + lr;
            if (r < M) {
                pa0 = *(const uint4*)(A + (size_t)r * 128 + lc * 16 + 0);
                pa1 = *(const uint4*)(A + (size_t)r * 128 + lc * 16 + 8);
            } else { pa0 = make_uint4(0,0,0,0); pa1 = make_uint4(0,0,0,0); }
            const float* wp = W1 + (size_t)tid * 128;
            #pragma unroll
            for (int q = 0; q < 4; q++) {
                float4 w0 = *(const float4*)(wp + q * 8 + 0);
                float4 w1 = *(const float4*)(wp + q * 8 + 4);
                pb[q] = make_uint4(pack2(w0.x, w0.y), pack2(w0.z, w0.w),
                                   pack2(w1.x, w1.y), pack2(w1.z, w1.w));
            }
        }
        // commit buf 0
        *(uint4*)&Asb[0][lr * LDA + lc * 16 + 0] = pa0;
        *(uint4*)&Asb[0][lr * LDA + lc * 16 + 8] = pa1;
        #pragma unroll
        for (int q = 0; q < 4; q++)
            *(uint4*)&Bsb[0][tid * LDA + q * 8] = pb[q];
        __syncthreads();

        #pragma unroll
        for (int it = 0; it < 4; it++) {
            int cur = it & 1;
            // prefetch next tile into regs
            if (it + 1 < 4) {
                int k0n = (it + 1) * 32;
                int r = row0 + lr;
                if (r < M) {
                    pa0 = *(const uint4*)(A + (size_t)r * 128 + k0n + lc * 16 + 0);
                    pa1 = *(const uint4*)(A + (size_t)r * 128 + k0n + lc * 16 + 8);
                } else { pa0 = make_uint4(0,0,0,0); pa1 = make_uint4(0,0,0,0); }
                const float* wp = W1 + (size_t)tid * 128 + k0n;
                #pragma unroll
                for (int q = 0; q < 4; q++) {
                    float4 w0 = *(const float4*)(wp + q * 8 + 0);
                    float4 w1 = *(const float4*)(wp + q * 8 + 4);
                    pb[q] = make_uint4(pack2(w0.x, w0.y), pack2(w0.z, w0.w),
                                       pack2(w1.x, w1.y), pack2(w1.z, w1.w));
                }
            }

            // mma from cur buffer
            #pragma unroll
            for (int s = 0; s < 2; s++) {
                uint32_t a[4][4], b[8][2];
                #pragma unroll
                for (int mt = 0; mt < 4; mt++) {
                    uint32_t sa = (uint32_t)__cvta_generic_to_shared(
                        &Asb[cur][(wM * 64 + mt * 16 + lm_roff) * LDA + s * 16 + lm_koff]);
                    LDSM_X4(a[mt][0], a[mt][1], a[mt][2], a[mt][3], sa);
                }
                #pragma unroll
                for (int ntp = 0; ntp < 4; ntp++) {
                    uint32_t sb = (uint32_t)__cvta_generic_to_shared(
                        &Bsb[cur][(wN * 64 + ntp * 16 + lm_roff) * LDA + s * 16 + lm_koff]);
                    uint32_t r0, r1, r2, r3;
                    LDSM_X4(r0, r1, r2, r3, sb);
                    b[2 * ntp][0]     = r0;
                    b[2 * ntp + 1][0] = r1;
                    b[2 * ntp][1]     = r2;
                    b[2 * ntp + 1][1] = r3;
                }
                #pragma unroll
                for (int mt = 0; mt < 4; mt++)
                    #pragma unroll
                    for (int nt = 0; nt < 8; nt++)
                        MMA_F16(c[mt][nt], a[mt], b[nt]);
            }

            // commit next tile to other buffer
            if (it + 1 < 4) {
                int nxt = 1 - cur;
                *(uint4*)&Asb[nxt][lr * LDA + lc * 16 + 0] = pa0;
                *(uint4*)&Asb[nxt][lr * LDA + lc * 16 + 8] = pa1;
                #pragma unroll
                for (int q = 0; q < 4; q++)
                    *(uint4*)&Bsb[nxt][tid * LDA + q * 8] = pb[q];
            }
            __syncthreads();
        }

        // relu + write h (fp16) to Hs
        #pragma unroll
        for (int mt = 0; mt < 4; mt++) {
            int r = wM * 64 + mt * 16 + gid;
            #pragma unroll
            for (int nt = 0; nt < 8; nt++) {
                int col = wN * 64 + nt * 8 + tig * 2;
                float v0 = fmaxf(c[mt][nt][0], 0.f), v1 = fmaxf(c[mt][nt][1], 0.f);
                float v2 = fmaxf(c[mt][nt][2], 0.f), v3 = fmaxf(c[mt][nt][3], 0.f);
                *(uint32_t*)&Hs[r * LDH + col]       = pack2(v0, v1);
                *(uint32_t*)&Hs[(r + 8) * LDH + col] = pack2(v2, v3);
            }
        }
    }
    __syncthreads();

    // ============ STAGE B: g = h @ W2^T, K=256, N=128 ============
    {
        float c[4][4][4] = {};

        uint4 pb0, pb1;    // W2 prefetch: row lr, 16 halves
        {
            const float* wp = W2 + (size_t)lr * 256 + lc * 16;
            float4 w0 = *(const float4*)(wp + 0);
            float4 w1 = *(const float4*)(wp + 4);
            float4 w2 = *(const float4*)(wp + 8);
            float4 w3 = *(const float4*)(wp + 12);
            pb0 = make_uint4(pack2(w0.x, w0.y), pack2(w0.z, w0.w),
                             pack2(w1.x, w1.y), pack2(w1.z, w1.w));
            pb1 = make_uint4(pack2(w2.x, w2.y), pack2(w2.z, w2.w),
                             pack2(w3.x, w3.y), pack2(w3.z, w3.w));
        }
        *(uint4*)&Asb[0][lr * LDA + lc * 16 + 0] = pb0;
        *(uint4*)&Asb[0][lr * LDA + lc * 16 + 8] = pb1;
        __syncthreads();

        #pragma unroll
        for (int it = 0; it < 8; it++) {
            int cur = it & 1;
            int k0  = it * 32;

            if (it + 1 < 8) {
                const float* wp = W2 + (size_t)lr * 256 + (it + 1) * 32 + lc * 16;
                float4 w0 = *(const float4*)(wp + 0);
                float4 w1 = *(const float4*)(wp + 4);
                float4 w2 = *(const float4*)(wp + 8);
                float4 w3 = *(const float4*)(wp + 12);
                pb0 = make_uint4(pack2(w0.x, w0.y), pack2(w0.z, w0.w),
                                 pack2(w1.x, w1.y), pack2(w1.z, w1.w));
                pb1 = make_uint4(pack2(w2.x, w2.y), pack2(w2.z, w2.w),
                                 pack2(w3.x, w3.y), pack2(w3.z, w3.w));
            }

            #pragma unroll
            for (int s = 0; s < 2; s++) {
                uint32_t a[4][4], b[4][2];
                #pragma unroll
                for (int mt = 0; mt < 4; mt++) {
                    uint32_t sa = (uint32_t)__cvta_generic_to_shared(
                        &Hs[(wM * 64 + mt * 16 + lm_roff) * LDH + k0 + s * 16 + lm_koff]);
                    LDSM_X4(a[mt][0], a[mt][1], a[mt][2], a[mt][3], sa);
                }
                #pragma unroll
                for (int ntp = 0; ntp < 2; ntp++) {
                    uint32_t sb = (uint32_t)__cvta_generic_to_shared(
                        &Asb[cur][(wN * 32 + ntp * 16 + lm_roff) * LDA + s * 16 + lm_koff]);
                    uint32_t r0, r1, r2, r3;
                    LDSM_X4(r0, r1, r2, r3, sb);
                    b[2 * ntp][0]     = r0;
                    b[2 * ntp + 1][0] = r1;
                    b[2 * ntp][1]     = r2;
                    b[2 * ntp + 1][1] = r3;
                }
                #pragma unroll
                for (int mt = 0; mt < 4; mt++)
                    #pragma unroll
                    for (int nt = 0; nt < 4; nt++)
                        MMA_F16(c[mt][nt], a[mt], b[nt]);
            }

            if (it + 1 < 8) {
                int nxt = 1 - cur;
                *(uint4*)&Asb[nxt][lr * LDA + lc * 16 + 0] = pb0;
                *(uint4*)&Asb[nxt][lr * LDA + lc * 16 + 8] = pb1;
            }
            __syncthreads();
        }

        // epilogue: g (fp16) to C
        #pragma unroll
        for (int mt = 0; mt < 4; mt++) {
            int r = row0 + wM * 64 + mt * 16 + gid;
            #pragma unroll
            for (int nt = 0; nt < 4; nt++) {
                int col = wN * 32 + nt * 8 + tig * 2;
                if (r < M)
                    *(uint32_t*)&C[(size_t)r * 128 + col] = pack2(c[mt][nt][0], c[mt][nt][1]);
                if (r + 8 < M)
                    *(uint32_t*)&C[(size_t)(r + 8) * 128 + col] = pack2(c[mt][nt][2], c[mt][nt][3]);
            }
        }
    }
}

// ---------------- launch ----------------
extern "C" void kernel_launch(void* const* d_in, const int* in_sizes, int n_in,
                              void* d_out, int out_size)
{
    const float* x  = (const float*)d_in[0];
    const int*   er = (const int*)  d_in[1];
    const int*   ec = (const int*)  d_in[2];
    const float* ev = (const float*)d_in[3];
    const float* W1 = (const float*)d_in[4];
    const float* W2 = (const float*)d_in[5];
    float* out = (float*)d_out;

    const int NB_E   = (NNZ + 255) / 256;            // 12500 (== N*128/4/256)
    const int NB_ROW = (N_NODES * 32 + 255) / 256;   // warp per row
    const int NB_S3  = (N_NODES + 255) / 256;

    cudaFuncSetAttribute(gemm_fused_kernel,
                         cudaFuncAttributeMaxDynamicSharedMemorySize, SMEM_FUSED);

    // ---- build CSR + convert x (fused hist/cvt; scan2 folded into scan3) ----
    hist_cvt_kernel<<<NB_E, 256>>>(er, x);
    scan1_kernel<<<SCAN_NB, SCAN_B>>>();
    scan3_kernel<<<NB_S3, 256>>>();
    scatter_kernel<<<NB_E, 256>>>(er, ec, ev);

    // ---- layer 1 propagation: s = A (A x16)  : sel0 -> sel1 -> sel2 ----
    spmm16_kernel<<<NB_ROW, 256>>>(0, 1, nullptr);
    spmm16_kernel<<<NB_ROW, 256>>>(1, 2, nullptr);

    // ---- fused: g = relu(s @ W1^T) @ W2^T : sel2 -> sel3 ----
    // (exact reorder: (A^2 h) W2^T == A^2 (h W2^T), propagate at d=128)
    gemm_fused_kernel<<<(N_NODES + 127) / 128, 256, SMEM_FUSED>>>(2, W1, W2, 3);

    // ---- layer 2 propagation: out = A (A g) : sel3 -> sel1 -> d_out(fp32) ----
    spmm16_kernel<<<NB_ROW, 256>>>(3, 1, nullptr);
    spmm16_kernel<<<NB_ROW, 256>>>(1, -1, out);
}